// round 2
// baseline (speedup 1.0000x reference)
#include <cuda_runtime.h>
#include <cstdint>

#define NPTS   131072
#define CIN    32
#define K3     27
#define CENTER 13
#define TP     128          // points per tile
#define NTHR   256
#define WS     36           // padded row stride (floats) to kill smem bank conflicts
#define WSZ    (K3*CIN*WS)  // 31104 floats

// ---------------- scratch (device globals; no allocation allowed) ----------
__device__ float g_Wt_ch[WSZ];          // W transposed [k][d][c], padded
__device__ float g_Wt_dw[WSZ];
__device__ float g_x[NPTS*CIN];         // conv1 output (16 MB)
__device__ float g_s[NPTS];
__device__ float g_norm[NPTS];
__device__ unsigned long long g_key[NPTS];
__device__ unsigned char g_mask[NPTS];
__device__ int g_list[NPTS];
__device__ int g_hist[2][256];
__device__ unsigned long long g_prefix[2];
__device__ int g_remain[2];
__device__ int g_count;
__device__ int g_nbpts;

#define SMEM_BYTES 175744

// decode a scalar that might arrive as int32/int64/float32 (dataset: th=1, nb=2)
__device__ int decode_small_int(const int* p, int fallback) {
    int v = p[0];
    if (v > 0 && v < (1 << 20)) return v;          // raw small int (int32 or int64 low word)
    float f = __int_as_float(v);
    if (f >= 1.f && f < 1048576.f && f == floorf(f)) return (int)f;  // float32
    return fallback;                               // e.g. float64 low word == 0
}

// ---------------- init: transpose weights, reset select state --------------
__global__ void init_kernel(const float* __restrict__ Wch, const float* __restrict__ Wdw,
                            const int* __restrict__ th_p, const int* __restrict__ nb_p)
{
    int tid = blockIdx.x * blockDim.x + threadIdx.x;
    const int total = K3 * CIN * CIN;
    for (int idx = tid; idx < total; idx += gridDim.x * blockDim.x) {
        int k = idx / (CIN * CIN);
        int rem = idx - k * CIN * CIN;
        int c = rem / CIN;
        int d = rem - c * CIN;
        g_Wt_ch[(k * CIN + d) * WS + c] = Wch[idx];
        g_Wt_dw[(k * CIN + d) * WS + c] = Wdw[idx];
    }
    if (tid == 0) {
        int th  = decode_small_int(th_p, 1);
        int nbb = decode_small_int(nb_p, 2);
        int nbpts = NPTS / nbb;
        g_nbpts = nbpts;
        int kk = (int)(((double)nbpts * (double)th) / 3.21);
        g_remain[0] = kk; g_remain[1] = kk;
        g_prefix[0] = 0ull; g_prefix[1] = 0ull;
        g_count = 0;
    }
    if (tid < 512) ((int*)g_hist)[tid] = 0;
}

// ---------------- fused gather-GEMM (conv1 and conv2) ----------------------
#define ACC1(P,D) \
    acc[P][D] += G##P.x * w##D.x; acc[P][D] += G##P.y * w##D.y; \
    acc[P][D] += G##P.z * w##D.z; acc[P][D] += G##P.w * w##D.w;
#define ACCROW(P) ACC1(P,0) ACC1(P,1) ACC1(P,2) ACC1(P,3)

template<bool SECOND>
__global__ void __launch_bounds__(NTHR, 1)
conv_kernel(const float* __restrict__ Fin,
            const float* __restrict__ bias,
            const int* __restrict__ nbr,
            float* __restrict__ out)
{
    extern __shared__ float smem[];
    float* sW   = smem;                       // WSZ floats
    float* sG   = sW + WSZ;                   // 2*TP*WS floats (double buffer)
    int*   sNbr = (int*)(sG + 2 * TP * WS);   // TP*K3
    int*   sPnt = sNbr + TP * K3;             // TP
    float* sb   = (float*)(sPnt + TP);        // CIN

    const int tid = threadIdx.x;
    const int t0 = blockIdx.x * TP;
    int rows = TP;
    if (SECOND) {
        const int cnt = g_count;
        if (t0 >= cnt) return;
        rows = min(TP, cnt - t0);
    }
    const float* F = SECOND ? g_x : Fin;
    const float* Wt = SECOND ? g_Wt_dw : g_Wt_ch;

    for (int i = tid; i < WSZ; i += NTHR) sW[i] = Wt[i];
    if (tid < CIN) sb[tid] = bias[tid];

    if (SECOND) {
        for (int r = tid; r < TP; r += NTHR) sPnt[r] = (r < rows) ? g_list[t0 + r] : -1;
        __syncthreads();
    }
    for (int i = tid; i < TP * K3; i += NTHR) {
        int r = i / K3, k = i - r * K3;
        int v;
        if (SECOND) {
            int n = sPnt[r];
            v = (n >= 0) ? nbr[(size_t)n * K3 + k] : -1;
            if (v >= 0 && !g_mask[v]) v = -1;   // gate: neighbor must be masked
        } else {
            v = nbr[(size_t)(t0 + r) * K3 + k];
        }
        sNbr[i] = v;
    }
    __syncthreads();

    float4 pre[4];
    // prefetch + stage k = 0
    #pragma unroll
    for (int j = 0; j < 4; j++) {
        int q = tid + j * NTHR; int row = q >> 3, quad = q & 7;
        int nb = sNbr[row * K3 + 0];
        pre[j] = (nb >= 0) ? __ldg((const float4*)(F + (size_t)nb * CIN) + quad)
                           : make_float4(0.f, 0.f, 0.f, 0.f);
    }
    #pragma unroll
    for (int j = 0; j < 4; j++) {
        int q = tid + j * NTHR; int row = q >> 3, quad = q & 7;
        *(float4*)(sG + row * WS + quad * 4) = pre[j];
    }
    __syncthreads();

    float acc[4][4];
    #pragma unroll
    for (int p = 0; p < 4; p++) { acc[p][0] = 0.f; acc[p][1] = 0.f; acc[p][2] = 0.f; acc[p][3] = 0.f; }

    const int pr = tid >> 3, cc = tid & 7;
    const float* gb0 = sG + pr * 4 * WS;
    const float* wb0 = sW + cc * 4 * WS;

    for (int k = 0; k < K3; k++) {
        if (k + 1 < K3) {
            #pragma unroll
            for (int j = 0; j < 4; j++) {
                int q = tid + j * NTHR; int row = q >> 3, quad = q & 7;
                int nb = sNbr[row * K3 + (k + 1)];
                pre[j] = (nb >= 0) ? __ldg((const float4*)(F + (size_t)nb * CIN) + quad)
                                   : make_float4(0.f, 0.f, 0.f, 0.f);
            }
        }
        const float* gb = gb0 + (k & 1) * TP * WS;
        const float* wb = wb0 + k * CIN * WS;
        #pragma unroll
        for (int c0 = 0; c0 < CIN; c0 += 4) {
            float4 w0 = *(const float4*)(wb + 0 * WS + c0);
            float4 w1 = *(const float4*)(wb + 1 * WS + c0);
            float4 w2 = *(const float4*)(wb + 2 * WS + c0);
            float4 w3 = *(const float4*)(wb + 3 * WS + c0);
            float4 G0 = *(const float4*)(gb + 0 * WS + c0);
            float4 G1 = *(const float4*)(gb + 1 * WS + c0);
            float4 G2 = *(const float4*)(gb + 2 * WS + c0);
            float4 G3 = *(const float4*)(gb + 3 * WS + c0);
            ACCROW(0) ACCROW(1) ACCROW(2) ACCROW(3)
        }
        if (k + 1 < K3) {
            // write next buffer (disjoint from the one being read), then sync
            #pragma unroll
            for (int j = 0; j < 4; j++) {
                int q = tid + j * NTHR; int row = q >> 3, quad = q & 7;
                *(float4*)(sG + ((k + 1) & 1) * TP * WS + row * WS + quad * 4) = pre[j];
            }
            __syncthreads();
        }
    }

    if (!SECOND) {
        #pragma unroll
        for (int p = 0; p < 4; p++) {
            int n = t0 + pr * 4 + p;
            float4 xv;
            xv.x = acc[p][0] + sb[cc * 4 + 0];
            xv.y = acc[p][1] + sb[cc * 4 + 1];
            xv.z = acc[p][2] + sb[cc * 4 + 2];
            xv.w = acc[p][3] + sb[cc * 4 + 3];
            *(float4*)(g_x + (size_t)n * CIN + cc * 4) = xv;
            float ps = xv.x + xv.y + xv.z + xv.w;
            float pn = xv.x * xv.x + xv.y * xv.y + xv.z * xv.z + xv.w * xv.w;
            #pragma unroll
            for (int o = 1; o < 8; o <<= 1) {
                ps += __shfl_xor_sync(0xffffffffu, ps, o);
                pn += __shfl_xor_sync(0xffffffffu, pn, o);
            }
            if (cc == 0) { g_s[n] = ps; g_norm[n] = pn; }
        }
    } else {
        #pragma unroll
        for (int p = 0; p < 4; p++) {
            int r = pr * 4 + p;
            if (r < rows) {
                int n = sPnt[r];
                float4 xr = *(const float4*)(g_x + (size_t)n * CIN + cc * 4);
                float4 ov;
                ov.x = acc[p][0] + sb[cc * 4 + 0] + xr.x;
                ov.y = acc[p][1] + sb[cc * 4 + 1] + xr.y;
                ov.z = acc[p][2] + sb[cc * 4 + 2] + xr.z;
                ov.w = acc[p][3] + sb[cc * 4 + 3] + xr.w;
                *(float4*)(out + (size_t)n * CIN + cc * 4) = ov;
            }
        }
    }
}

// ---------------- corr + sortable key ---------------------------------------
__global__ void corr_kernel(const int* __restrict__ nbr)
{
    int n = blockIdx.x * blockDim.x + threadIdx.x;
    if (n >= NPTS) return;
    const int* row = nbr + (size_t)n * K3;
    float sum = 0.f;
    #pragma unroll
    for (int k = 0; k < K3; k++) {
        if (k == CENTER) continue;
        int nb = row[k];
        if (nb >= 0) sum += __ldg(&g_s[nb]);
    }
    float corr = sum / g_norm[n];
    unsigned u = __float_as_uint(corr);
    u ^= (u & 0x80000000u) ? 0xFFFFFFFFu : 0x80000000u;   // monotonic map
    unsigned li = (unsigned)(n % g_nbpts);
    // 48-bit key: larger value wins; ties -> smaller index wins
    g_key[n] = ((unsigned long long)u << 16) | (unsigned long long)(0xFFFFu - li);
}

// ---------------- exact radix select (6 x 8-bit rounds, MSB first) ---------
__global__ void hist_kernel(int shift)
{
    __shared__ int h[256];
    const int nbpts = g_nbpts;
    const int b = blockIdx.y;
    for (int i = threadIdx.x; i < 256; i += blockDim.x) h[i] = 0;
    __syncthreads();
    const unsigned long long pref = g_prefix[b] >> (shift + 8);
    for (int i = blockIdx.x * blockDim.x + threadIdx.x; i < nbpts; i += gridDim.x * blockDim.x) {
        unsigned long long key = g_key[(size_t)b * nbpts + i];
        if ((key >> (shift + 8)) == pref)
            atomicAdd(&h[(int)((key >> shift) & 255)], 1);
    }
    __syncthreads();
    for (int i = threadIdx.x; i < 256; i += blockDim.x) {
        int v = h[i];
        if (v) atomicAdd(&g_hist[b][i], v);
    }
}

__global__ void pick_kernel(int shift)
{
    __shared__ int h[256];
    const int b = blockIdx.x;
    for (int i = threadIdx.x; i < 256; i += blockDim.x) h[i] = g_hist[b][i];
    __syncthreads();
    if (threadIdx.x == 0) {
        int remain = g_remain[b];
        int cum = 0, d = 0;
        for (int j = 255; j >= 0; --j) {
            int c = h[j];
            if (cum + c >= remain) { d = j; break; }
            cum += c;
        }
        g_prefix[b] |= ((unsigned long long)d) << shift;
        g_remain[b] = remain - cum;
    }
    __syncthreads();
    for (int i = threadIdx.x; i < 256; i += blockDim.x) g_hist[b][i] = 0;
}

// ---------------- mask + compaction -----------------------------------------
__global__ void mask_kernel()
{
    int n = blockIdx.x * blockDim.x + threadIdx.x;
    if (n >= NPTS) return;
    int b = n / g_nbpts;
    bool m = g_key[n] >= g_prefix[b];   // exactly k keys per batch (keys distinct)
    g_mask[n] = m ? 1 : 0;
    if (m) { int pos = atomicAdd(&g_count, 1); g_list[pos] = n; }
}

// ---------------- baseline out = 2*x (masked rows overwritten by conv2) ----
__global__ void scale2_kernel(float* __restrict__ out)
{
    int i = blockIdx.x * blockDim.x + threadIdx.x;
    if (i < NPTS * CIN / 4) {
        float4 v = ((const float4*)g_x)[i];
        ((float4*)out)[i] = make_float4(v.x + v.x, v.y + v.y, v.z + v.z, v.w + v.w);
    }
}

// ---------------------------------------------------------------------------
extern "C" void kernel_launch(void* const* d_in, const int* in_sizes, int n_in,
                              void* d_out, int out_size)
{
    const float* xF  = (const float*)d_in[0];
    const float* Wch = (const float*)d_in[1];
    const float* bch = (const float*)d_in[2];
    const float* Wdw = (const float*)d_in[3];
    const float* bdw = (const float*)d_in[4];
    const int*   nbr = (const int*)d_in[5];
    const int*   th  = (const int*)d_in[6];
    const int*   nbb = (const int*)d_in[7];
    float* out = (float*)d_out;

    cudaFuncSetAttribute(conv_kernel<false>, cudaFuncAttributeMaxDynamicSharedMemorySize, SMEM_BYTES);
    cudaFuncSetAttribute(conv_kernel<true>,  cudaFuncAttributeMaxDynamicSharedMemorySize, SMEM_BYTES);

    init_kernel<<<32, 256>>>(Wch, Wdw, th, nbb);
    conv_kernel<false><<<NPTS / TP, NTHR, SMEM_BYTES>>>(xF, bch, nbr, out);
    corr_kernel<<<NPTS / 256, 256>>>(nbr);
    const int shifts[6] = {40, 32, 24, 16, 8, 0};
    for (int r = 0; r < 6; r++) {
        hist_kernel<<<dim3(64, 2), 256>>>(shifts[r]);
        pick_kernel<<<2, 256>>>(shifts[r]);
    }
    mask_kernel<<<NPTS / 256, 256>>>();
    scale2_kernel<<<NPTS * CIN / 4 / 256, 256>>>(out);
    conv_kernel<true><<<NPTS / TP, NTHR, SMEM_BYTES>>>(xF, bdw, nbr, out);
}

// round 3
// speedup vs baseline: 2.0029x; 2.0029x over previous
#include <cuda_runtime.h>
#include <cstdint>

#define NPTS   131072
#define K3     27
#define CENTER 13
#define TPB    256
#define TP     512

__device__ __align__(16) float g_x[NPTS*32];
__device__ float g_s[NPTS];
__device__ float g_norm[NPTS];
__device__ unsigned long long g_key[NPTS];
__device__ unsigned char g_mask[NPTS];
__device__ int g_list[NPTS];
__device__ int g_hist[2][4096];
__device__ unsigned long long g_prefix[2];
__device__ int g_remain[2];
__device__ int g_count;
__device__ int g_nbpts;

// smem floats: sG 2*512*32 | sW 2*1024 | sPnt 512 | sb 32
#define SW_OFF     32768
#define SPNT_OFF   34816
#define SB_OFF     35328
#define SMEM_BYTES ((SB_OFF + 32) * 4)

__device__ __forceinline__ void fma2(unsigned long long &d, unsigned long long a,
                                     unsigned long long b) {
    asm("fma.rn.f32x2 %0, %1, %2, %0;" : "+l"(d) : "l"(a), "l"(b));
}
__device__ __forceinline__ unsigned long long pack2(float v) {
    unsigned long long r;
    asm("mov.b64 %0, {%1, %1};" : "=l"(r) : "f"(v));
    return r;
}
__device__ __forceinline__ void unpack2(float &lo, float &hi, unsigned long long v) {
    asm("mov.b64 {%0, %1}, %2;" : "=f"(lo), "=f"(hi) : "l"(v));
}
__device__ __forceinline__ void cpa16(uint32_t dst, const void* src, int sz) {
    asm volatile("cp.async.ca.shared.global [%0], [%1], 16, %2;"
                 :: "r"(dst), "l"(src), "r"(sz) : "memory");
}
__device__ __forceinline__ void cpa_commit() { asm volatile("cp.async.commit_group;" ::: "memory"); }
__device__ __forceinline__ void cpa_wait0()  { asm volatile("cp.async.wait_group 0;"  ::: "memory"); }

__device__ int decode_small_int(const int* p, int fallback) {
    int v = p[0];
    if (v > 0 && v < (1 << 20)) return v;
    float f = __int_as_float(v);
    if (f >= 1.f && f < 1048576.f && f == floorf(f)) return (int)f;
    return fallback;
}

__global__ void init_kernel(const int* __restrict__ th_p, const int* __restrict__ nb_p)
{
    int tid = blockIdx.x * blockDim.x + threadIdx.x;
    if (tid == 0) {
        int th  = decode_small_int(th_p, 1);
        int nbb = decode_small_int(nb_p, 2);
        int nbpts = NPTS / nbb;
        g_nbpts = nbpts;
        int kk = (int)(((double)nbpts * (double)th) / 3.21);
        g_remain[0] = kk; g_remain[1] = kk;
        g_prefix[0] = 0ull; g_prefix[1] = 0ull;
        g_count = 0;
    }
    if (tid < 8192) ((int*)g_hist)[tid] = 0;
}

// ------------- fused gather-GEMM: thread-owns-point, f32x2 accumulators ----
template<bool SECOND>
__global__ void __launch_bounds__(TPB, 1)
conv_kernel(const float* __restrict__ Fin,
            const float* __restrict__ W,      // [k][c][d] 27*32*32
            const float* __restrict__ bias,
            const int* __restrict__ nbr,
            float* __restrict__ out)
{
    extern __shared__ float smem[];
    float* sG   = smem;
    float* sW   = smem + SW_OFF;
    int*   sPnt = (int*)(smem + SPNT_OFF);
    float* sb   = smem + SB_OFF;

    const int tid = threadIdx.x;
    const int t0  = blockIdx.x * TP;
    const float* F = SECOND ? g_x : Fin;

    int cnt = 0;
    if (SECOND) {
        cnt = g_count;
        if (t0 >= cnt) return;
    }
    if (tid < 32) sb[tid] = bias[tid];
    if (SECOND) {
        for (int r = tid; r < TP; r += TPB)
            sPnt[r] = (t0 + r < cnt) ? g_list[t0 + r] : -1;
    }
    __syncthreads();

    const uint32_t sg_u = (uint32_t)__cvta_generic_to_shared(sG);
    const uint32_t sw_u = (uint32_t)__cvta_generic_to_shared(sW);

    auto stage = [&](int k, int buf) {
        uint32_t gbase = sg_u + buf * 65536;
        #pragma unroll
        for (int j = 0; j < 16; j++) {
            int idx = (j << 8) + tid;          // (pt, quad)
            int pt = idx >> 3, q = idx & 7;
            int n = SECOND ? sPnt[pt] : (t0 + pt);
            int nb = -1;
            if (n >= 0) nb = __ldg(nbr + (size_t)n * K3 + k);
            if (SECOND && nb >= 0 && !g_mask[nb]) nb = -1;
            const char* src = (const char*)(F + ((size_t)(nb < 0 ? 0 : nb) << 5)) + (q << 4);
            uint32_t dst = gbase + (pt << 7) + (((q ^ pt) & 7) << 4);   // XOR swizzle
            cpa16(dst, src, nb >= 0 ? 16 : 0);
        }
        cpa16(sw_u + buf * 4096 + tid * 16, W + (size_t)k * 1024 + tid * 4, 16);
    };

    stage(0, 0);
    cpa_commit();
    cpa_wait0();
    __syncthreads();

    unsigned long long acc0[16], acc1[16];
    #pragma unroll
    for (int i = 0; i < 16; i++) { acc0[i] = 0ull; acc1[i] = 0ull; }

    const int pt0 = tid, pt1 = tid + 256;
    for (int k = 0; k < K3; k++) {
        if (k + 1 < K3) { stage(k + 1, (k + 1) & 1); cpa_commit(); }
        const float* gbuf = sG + (k & 1) * 16384;
        const float* wbuf = sW + (k & 1) * 1024;
        const float* g0p = gbuf + (pt0 << 5);
        const float* g1p = gbuf + (pt1 << 5);
        #pragma unroll
        for (int c4 = 0; c4 < 8; c4++) {
            float4 ga  = *(const float4*)(g0p + (((c4 ^ pt0) & 7) << 2));
            float4 gbv = *(const float4*)(g1p + (((c4 ^ pt1) & 7) << 2));
            #pragma unroll
            for (int m = 0; m < 4; m++) {
                const int c = (c4 << 2) + m;
                float fa = (m == 0) ? ga.x  : (m == 1) ? ga.y  : (m == 2) ? ga.z  : ga.w;
                float fb = (m == 0) ? gbv.x : (m == 1) ? gbv.y : (m == 2) ? gbv.z : gbv.w;
                unsigned long long u0 = pack2(fa), u1 = pack2(fb);
                const ulonglong2* wr = (const ulonglong2*)(wbuf + (c << 5));
                #pragma unroll
                for (int d = 0; d < 8; d++) {
                    ulonglong2 wv = wr[d];          // lane-invariant broadcast
                    fma2(acc0[2*d],   u0, wv.x);
                    fma2(acc0[2*d+1], u0, wv.y);
                    fma2(acc1[2*d],   u1, wv.x);
                    fma2(acc1[2*d+1], u1, wv.y);
                }
            }
        }
        if (k + 1 < K3) { cpa_wait0(); __syncthreads(); }
    }

    #pragma unroll
    for (int half = 0; half < 2; half++) {
        unsigned long long* acc = half ? acc1 : acc0;
        int pt = half ? pt1 : pt0;
        int n = SECOND ? sPnt[pt] : (t0 + pt);
        if (SECOND && n < 0) continue;
        float r[32];
        #pragma unroll
        for (int i = 0; i < 16; i++) {
            float lo, hi;
            unpack2(lo, hi, acc[i]);
            r[2*i]   = lo + sb[2*i];
            r[2*i+1] = hi + sb[2*i+1];
        }
        if (!SECOND) {
            float s = 0.f, nm = 0.f;
            #pragma unroll
            for (int i = 0; i < 32; i++) { s += r[i]; nm += r[i] * r[i]; }
            #pragma unroll
            for (int i = 0; i < 8; i++)
                *(float4*)(g_x + ((size_t)n << 5) + i * 4) =
                    make_float4(r[4*i], r[4*i+1], r[4*i+2], r[4*i+3]);
            g_s[n] = s;
            g_norm[n] = nm;
        } else {
            #pragma unroll
            for (int i = 0; i < 8; i++) {
                float4 xv = *(const float4*)(g_x + ((size_t)n << 5) + i * 4);
                *(float4*)(out + ((size_t)n << 5) + i * 4) =
                    make_float4(r[4*i] + xv.x, r[4*i+1] + xv.y,
                                r[4*i+2] + xv.z, r[4*i+3] + xv.w);
            }
        }
    }
}

__global__ void corr_kernel(const int* __restrict__ nbr)
{
    int n = blockIdx.x * blockDim.x + threadIdx.x;
    if (n >= NPTS) return;
    const int* row = nbr + (size_t)n * K3;
    float sum = 0.f;
    #pragma unroll
    for (int k = 0; k < K3; k++) {
        if (k == CENTER) continue;
        int nb = row[k];
        if (nb >= 0) sum += __ldg(&g_s[nb]);
    }
    float corr = sum / g_norm[n];
    unsigned u = __float_as_uint(corr);
    u ^= (u & 0x80000000u) ? 0xFFFFFFFFu : 0x80000000u;
    unsigned li = (unsigned)(n % g_nbpts);
    g_key[n] = ((unsigned long long)u << 16) | (unsigned long long)(0xFFFFu - li);
}

// ------------- exact radix select: 4 x 12-bit rounds, MSB first ------------
__global__ void hist_kernel(int shift)
{
    __shared__ int h[4096];
    const int nbpts = g_nbpts;
    const int b = blockIdx.y;
    for (int i = threadIdx.x; i < 4096; i += blockDim.x) h[i] = 0;
    __syncthreads();
    const unsigned long long pref = g_prefix[b] >> (shift + 12);
    for (int i = blockIdx.x * blockDim.x + threadIdx.x; i < nbpts; i += gridDim.x * blockDim.x) {
        unsigned long long key = g_key[(size_t)b * nbpts + i];
        if ((key >> (shift + 12)) == pref)
            atomicAdd(&h[(int)((key >> shift) & 4095)], 1);
    }
    __syncthreads();
    for (int i = threadIdx.x; i < 4096; i += blockDim.x) {
        int v = h[i];
        if (v) atomicAdd(&g_hist[b][i], v);
    }
}

__global__ void pick_kernel(int shift)
{
    __shared__ int tsum[256];
    __shared__ int tsuf[257];
    const int b = blockIdx.x;
    const int t = threadIdx.x;
    const int remain = g_remain[b];
    int loc[16]; int s = 0;
    const int base = t * 16;
    #pragma unroll
    for (int i = 0; i < 16; i++) { loc[i] = g_hist[b][base + i]; s += loc[i]; }
    tsum[t] = s;
    __syncthreads();
    if (t == 0) {
        int a = 0; tsuf[256] = 0;
        for (int i = 255; i >= 0; --i) { a += tsum[i]; tsuf[i] = a; }
    }
    __syncthreads();
    int suf = tsuf[t + 1];                 // count of keys with digit > base+15
    for (int i = 15; i >= 0; --i) {
        int snew = suf + loc[i];           // count with digit >= base+i
        if (snew >= remain && suf < remain) {
            g_prefix[b] |= ((unsigned long long)(base + i)) << shift;
            g_remain[b] = remain - suf;
        }
        suf = snew;
    }
    #pragma unroll
    for (int i = 0; i < 16; i++) g_hist[b][base + i] = 0;
}

__global__ void mask_kernel()
{
    int n = blockIdx.x * blockDim.x + threadIdx.x;
    if (n >= NPTS) return;
    int b = n / g_nbpts;
    bool m = g_key[n] >= g_prefix[b];
    g_mask[n] = m ? 1 : 0;
    if (m) { int pos = atomicAdd(&g_count, 1); g_list[pos] = n; }
}

__global__ void scale2_kernel(float* __restrict__ out)
{
    int i = blockIdx.x * blockDim.x + threadIdx.x;
    if (i < NPTS * 32 / 4) {
        float4 v = ((const float4*)g_x)[i];
        ((float4*)out)[i] = make_float4(v.x + v.x, v.y + v.y, v.z + v.z, v.w + v.w);
    }
}

extern "C" void kernel_launch(void* const* d_in, const int* in_sizes, int n_in,
                              void* d_out, int out_size)
{
    const float* xF  = (const float*)d_in[0];
    const float* Wch = (const float*)d_in[1];
    const float* bch = (const float*)d_in[2];
    const float* Wdw = (const float*)d_in[3];
    const float* bdw = (const float*)d_in[4];
    const int*   nbr = (const int*)d_in[5];
    const int*   th  = (const int*)d_in[6];
    const int*   nbb = (const int*)d_in[7];
    float* out = (float*)d_out;

    cudaFuncSetAttribute(conv_kernel<false>, cudaFuncAttributeMaxDynamicSharedMemorySize, SMEM_BYTES);
    cudaFuncSetAttribute(conv_kernel<true>,  cudaFuncAttributeMaxDynamicSharedMemorySize, SMEM_BYTES);

    init_kernel<<<32, 256>>>(th, nbb);
    conv_kernel<false><<<NPTS / TP, TPB, SMEM_BYTES>>>(xF, Wch, bch, nbr, out);
    corr_kernel<<<NPTS / 256, 256>>>(nbr);
    const int shifts[4] = {36, 24, 12, 0};
    for (int r = 0; r < 4; r++) {
        hist_kernel<<<dim3(64, 2), 256>>>(shifts[r]);
        pick_kernel<<<2, 256>>>(shifts[r]);
    }
    mask_kernel<<<NPTS / 256, 256>>>();
    scale2_kernel<<<NPTS * 32 / 4 / 256, 256>>>(out);
    conv_kernel<true><<<NPTS / TP, TPB, SMEM_BYTES>>>(xF, Wdw, bdw, nbr, out);
}